// round 4
// baseline (speedup 1.0000x reference)
#include <cuda_runtime.h>
#include <cuda_bf16.h>
#include <cstdint>

// ---------------------------------------------------------------------------
// GraphConvolution: out = SpMM(COO adj, x @ W) + bias
// Round 3: (a) register-staged pipelined tf32 GEMM, (b) gather split so each
// output row is covered by 4 warps (quarter-row each) with 4-edge unroll.
// ---------------------------------------------------------------------------

#define D 512
#define MAX_NODES 50000
#define MAX_EDGES 400000

__device__ float g_support[(size_t)MAX_NODES * D];
__device__ int   g_counts[MAX_NODES];
__device__ int   g_offsets[MAX_NODES + 1];
__device__ int   g_cursors[MAX_NODES];
__device__ int2  g_perm[MAX_EDGES];      // (col, val-as-int) sorted by row

// ---------------------------------------------------------------------------
// Prep 1: zero histogram
// ---------------------------------------------------------------------------
__global__ void zero_counts_kernel(int n) {
    int i = blockIdx.x * blockDim.x + threadIdx.x;
    if (i < n) g_counts[i] = 0;
}

// ---------------------------------------------------------------------------
// Prep 2: histogram of destination rows
// ---------------------------------------------------------------------------
__global__ void hist_kernel(const int* __restrict__ rows, int E) {
    int e = blockIdx.x * blockDim.x + threadIdx.x;
    if (e < E) atomicAdd(&g_counts[rows[e]], 1);
}

// ---------------------------------------------------------------------------
// Prep 3: exclusive scan (single block, 1024 threads, iterative with carry)
// ---------------------------------------------------------------------------
__global__ __launch_bounds__(1024)
void scan_kernel(int n) {
    __shared__ int warp_sums[32];
    __shared__ int s_carry;
    const int tid  = threadIdx.x;
    const int lane = tid & 31;
    const int wid  = tid >> 5;

    if (tid == 0) s_carry = 0;
    __syncthreads();

    for (int base = 0; base < n; base += 1024) {
        const int i = base + tid;
        const int v = (i < n) ? g_counts[i] : 0;

        int x = v;
        #pragma unroll
        for (int d = 1; d < 32; d <<= 1) {
            int y = __shfl_up_sync(0xffffffffu, x, d);
            if (lane >= d) x += y;
        }
        if (lane == 31) warp_sums[wid] = x;
        __syncthreads();

        if (wid == 0) {
            int w = warp_sums[lane];
            #pragma unroll
            for (int d = 1; d < 32; d <<= 1) {
                int y = __shfl_up_sync(0xffffffffu, w, d);
                if (lane >= d) w += y;
            }
            warp_sums[lane] = w;
        }
        __syncthreads();

        const int warp_prefix = (wid == 0) ? 0 : warp_sums[wid - 1];
        const int excl = s_carry + warp_prefix + x - v;
        if (i < n) {
            g_offsets[i] = excl;
            g_cursors[i] = excl;
        }
        const int block_total = warp_sums[31];
        __syncthreads();
        if (tid == 0) s_carry += block_total;
        __syncthreads();
    }
    if (tid == 0) g_offsets[n] = s_carry;
}

// ---------------------------------------------------------------------------
// Prep 4: placement
// ---------------------------------------------------------------------------
__global__ void place_kernel(const int* __restrict__ rows,
                             const int* __restrict__ cols,
                             const float* __restrict__ vals,
                             int E) {
    int e = blockIdx.x * blockDim.x + threadIdx.x;
    if (e >= E) return;
    int pos = atomicAdd(&g_cursors[rows[e]], 1);
    g_perm[pos] = make_int2(cols[e], __float_as_int(vals[e]));
}

// ---------------------------------------------------------------------------
// TF32 tensor-core GEMM, register-staged pipeline.
// CTA tile 128x128x16, 8 warps (4x2), warp tile 32x64, mma.m16n8k8.tf32.
// ---------------------------------------------------------------------------
#define BM 128
#define BN 128
#define BK 16
#define SSTRIDE (BM + 8)   // 136 % 32 == 8 -> conflict-free fragment LDS

__device__ __forceinline__ uint32_t f32_to_tf32(float f) {
    uint32_t r;
    asm("cvt.rna.tf32.f32 %0, %1;" : "=r"(r) : "f"(f));
    return r;
}

__global__ __launch_bounds__(256, 2)
void tf32_gemm_kernel(const float* __restrict__ A,
                      const float* __restrict__ B,
                      float* __restrict__ C,
                      int M) {
    constexpr int N = 512, K = 512;

    __shared__ uint32_t As[BK][SSTRIDE];
    __shared__ uint32_t Bs[BK][SSTRIDE];

    const int tid  = threadIdx.x;
    const int wid  = tid >> 5;
    const int lane = tid & 31;
    const int g    = lane >> 2;
    const int tg   = lane & 3;

    const int wm = (wid >> 1) * 32;
    const int wn = (wid & 1) * 64;

    const int m_base = blockIdx.y * BM;
    const int n_base = blockIdx.x * BN;

    // loader coordinates (2 float4 each for A and B per thread)
    const int a_row0 = tid >> 1;                 // via f = tid*2+j: rows tid/2
    // A: f = tid*2+j -> row = f>>2, kq = (f&3)*4
    // B: f = tid*2+j -> brow = f>>5, bc4 = (f&31)*4

    float acc[2][8][4];
    #pragma unroll
    for (int mi = 0; mi < 2; mi++)
        #pragma unroll
        for (int ni = 0; ni < 8; ni++)
            #pragma unroll
            for (int r = 0; r < 4; r++) acc[mi][ni][r] = 0.0f;

    float4 a_stage[2], b_stage[2];

    // ---- prologue: fetch tile k0 = 0 into registers ----
    #pragma unroll
    for (int j = 0; j < 2; j++) {
        const int f   = tid * 2 + j;
        const int row = f >> 2;
        const int kq  = (f & 3) * 4;
        a_stage[j] = make_float4(0.f, 0.f, 0.f, 0.f);
        if (m_base + row < M)
            a_stage[j] = *reinterpret_cast<const float4*>(
                             A + (size_t)(m_base + row) * K + kq);
        const int brow = f >> 5;
        const int bc4  = (f & 31) * 4;
        b_stage[j] = *reinterpret_cast<const float4*>(
                         B + (size_t)brow * N + n_base + bc4);
    }

    for (int k0 = 0; k0 < K; k0 += BK) {
        // ---- commit staged tile to smem ----
        #pragma unroll
        for (int j = 0; j < 2; j++) {
            const int f   = tid * 2 + j;
            const int row = f >> 2;
            const int kq  = (f & 3) * 4;
            As[kq + 0][row] = f32_to_tf32(a_stage[j].x);
            As[kq + 1][row] = f32_to_tf32(a_stage[j].y);
            As[kq + 2][row] = f32_to_tf32(a_stage[j].z);
            As[kq + 3][row] = f32_to_tf32(a_stage[j].w);
            const int brow = f >> 5;
            const int bc4  = (f & 31) * 4;
            uint4 t;
            t.x = f32_to_tf32(b_stage[j].x);
            t.y = f32_to_tf32(b_stage[j].y);
            t.z = f32_to_tf32(b_stage[j].z);
            t.w = f32_to_tf32(b_stage[j].w);
            *reinterpret_cast<uint4*>(&Bs[brow][bc4]) = t;
        }
        __syncthreads();

        // ---- prefetch next tile into registers (overlaps with compute) ----
        const int k1 = k0 + BK;
        if (k1 < K) {
            #pragma unroll
            for (int j = 0; j < 2; j++) {
                const int f   = tid * 2 + j;
                const int row = f >> 2;
                const int kq  = (f & 3) * 4;
                a_stage[j] = make_float4(0.f, 0.f, 0.f, 0.f);
                if (m_base + row < M)
                    a_stage[j] = *reinterpret_cast<const float4*>(
                                     A + (size_t)(m_base + row) * K + k1 + kq);
                const int brow = f >> 5;
                const int bc4  = (f & 31) * 4;
                b_stage[j] = *reinterpret_cast<const float4*>(
                                 B + (size_t)(k1 + brow) * N + n_base + bc4);
            }
        }

        // ---- compute on current smem tile ----
        #pragma unroll
        for (int ks = 0; ks < BK; ks += 8) {
            uint32_t a[2][4], b[8][2];
            #pragma unroll
            for (int mi = 0; mi < 2; mi++) {
                const int m0 = wm + mi * 16;
                a[mi][0] = As[ks + tg    ][m0 + g    ];
                a[mi][1] = As[ks + tg    ][m0 + g + 8];
                a[mi][2] = As[ks + tg + 4][m0 + g    ];
                a[mi][3] = As[ks + tg + 4][m0 + g + 8];
            }
            #pragma unroll
            for (int ni = 0; ni < 8; ni++) {
                const int n0 = wn + ni * 8;
                b[ni][0] = Bs[ks + tg    ][n0 + g];
                b[ni][1] = Bs[ks + tg + 4][n0 + g];
            }
            #pragma unroll
            for (int mi = 0; mi < 2; mi++)
                #pragma unroll
                for (int ni = 0; ni < 8; ni++) {
                    asm volatile(
                        "mma.sync.aligned.m16n8k8.row.col.f32.tf32.tf32.f32 "
                        "{%0,%1,%2,%3}, {%4,%5,%6,%7}, {%8,%9}, {%0,%1,%2,%3};"
                        : "+f"(acc[mi][ni][0]), "+f"(acc[mi][ni][1]),
                          "+f"(acc[mi][ni][2]), "+f"(acc[mi][ni][3])
                        : "r"(a[mi][0]), "r"(a[mi][1]), "r"(a[mi][2]), "r"(a[mi][3]),
                          "r"(b[ni][0]), "r"(b[ni][1]));
                }
        }
        __syncthreads();
    }

    #pragma unroll
    for (int mi = 0; mi < 2; mi++) {
        const int row0 = m_base + wm + mi * 16 + g;
        const int row1 = row0 + 8;
        #pragma unroll
        for (int ni = 0; ni < 8; ni++) {
            const int col = n_base + wn + ni * 8 + 2 * tg;
            if (row0 < M) {
                float2 v = make_float2(acc[mi][ni][0], acc[mi][ni][1]);
                *reinterpret_cast<float2*>(C + (size_t)row0 * N + col) = v;
            }
            if (row1 < M) {
                float2 v = make_float2(acc[mi][ni][2], acc[mi][ni][3]);
                *reinterpret_cast<float2*>(C + (size_t)row1 * N + col) = v;
            }
        }
    }
}

// ---------------------------------------------------------------------------
// Row-gather, split: 4 warps per output row, each owns a 128-float quarter.
// Each lane accumulates one float4; 4-edge unroll for MLP.
// ---------------------------------------------------------------------------
__global__ __launch_bounds__(256)
void row_gather_kernel(const float* __restrict__ bias,
                       float* __restrict__ out,
                       int n_rows) {
    const int gw   = (blockIdx.x * blockDim.x + threadIdx.x) >> 5;
    const int lane = threadIdx.x & 31;
    const int row  = gw >> 2;       // output row
    const int part = gw & 3;        // quarter-row 0..3
    if (row >= n_rows) return;

    const int s = g_offsets[row];
    const int e = g_offsets[row + 1];
    const int fo = part * 32 + lane;   // float4 index within row, 0..127

    float4 acc = make_float4(0.f, 0.f, 0.f, 0.f);

    int i = s;
    for (; i + 3 < e; i += 4) {
        const int2 cv0 = g_perm[i];
        const int2 cv1 = g_perm[i + 1];
        const int2 cv2 = g_perm[i + 2];
        const int2 cv3 = g_perm[i + 3];
        const float4 m0 = reinterpret_cast<const float4*>(
                              g_support + (size_t)cv0.x * D)[fo];
        const float4 m1 = reinterpret_cast<const float4*>(
                              g_support + (size_t)cv1.x * D)[fo];
        const float4 m2 = reinterpret_cast<const float4*>(
                              g_support + (size_t)cv2.x * D)[fo];
        const float4 m3 = reinterpret_cast<const float4*>(
                              g_support + (size_t)cv3.x * D)[fo];
        const float v0 = __int_as_float(cv0.y);
        const float v1 = __int_as_float(cv1.y);
        const float v2 = __int_as_float(cv2.y);
        const float v3 = __int_as_float(cv3.y);
        acc.x += v0 * m0.x + v1 * m1.x + v2 * m2.x + v3 * m3.x;
        acc.y += v0 * m0.y + v1 * m1.y + v2 * m2.y + v3 * m3.y;
        acc.z += v0 * m0.z + v1 * m1.z + v2 * m2.z + v3 * m3.z;
        acc.w += v0 * m0.w + v1 * m1.w + v2 * m2.w + v3 * m3.w;
    }
    for (; i < e; i++) {
        const int2 cv = g_perm[i];
        const float v = __int_as_float(cv.y);
        const float4 m = reinterpret_cast<const float4*>(
                             g_support + (size_t)cv.x * D)[fo];
        acc.x += v * m.x;
        acc.y += v * m.y;
        acc.z += v * m.z;
        acc.w += v * m.w;
    }

    const float4 b = reinterpret_cast<const float4*>(bias)[fo];
    float4 r;
    r.x = acc.x + b.x;
    r.y = acc.y + b.y;
    r.z = acc.z + b.z;
    r.w = acc.w + b.w;
    reinterpret_cast<float4*>(out + (size_t)row * D)[fo] = r;
}

// ---------------------------------------------------------------------------
// Launch
// ---------------------------------------------------------------------------
extern "C" void kernel_launch(void* const* d_in, const int* in_sizes, int n_in,
                              void* d_out, int out_size) {
    const float* x        = (const float*)d_in[0];
    const int*   adj_rows = (const int*)  d_in[1];
    const int*   adj_cols = (const int*)  d_in[2];
    const float* adj_vals = (const float*)d_in[3];
    const float* weight   = (const float*)d_in[4];
    const float* bias     = (const float*)d_in[5];
    float* out = (float*)d_out;

    const int M = in_sizes[0] / D;   // N_NODES
    const int E = in_sizes[1];       // N_EDGES

    // --- CSR prep (counting sort by destination row) ---
    zero_counts_kernel<<<(M + 255) / 256, 256>>>(M);
    hist_kernel<<<(E + 255) / 256, 256>>>(adj_rows, E);
    scan_kernel<<<1, 1024>>>(M);
    place_kernel<<<(E + 255) / 256, 256>>>(adj_rows, adj_cols, adj_vals, E);

    // --- support = x @ W (tf32 tensor cores, pipelined) ---
    {
        float* support;
        cudaGetSymbolAddress((void**)&support, g_support);
        dim3 grid(D / BN, (M + BM - 1) / BM);
        tf32_gemm_kernel<<<grid, 256>>>(x, weight, support, M);
    }

    // --- out[r] = sum_{edges->r} val * support[col] + bias ---
    {
        int total_warps = 4 * M;
        int warps_per_block = 256 / 32;
        int blocks = (total_warps + warps_per_block - 1) / warps_per_block;
        row_gather_kernel<<<blocks, 256>>>(bias, out, M);
    }
}

// round 6
// speedup vs baseline: 1.0553x; 1.0553x over previous
#include <cuda_runtime.h>
#include <cuda_bf16.h>
#include <cstdint>

// ---------------------------------------------------------------------------
// GraphConvolution: out = SpMM(COO adj, x @ W) + bias
// Round 5: revert GEMM to mma.sync tf32 (tcgen05 rejected by this toolchain's
// compute_103 PTX target). Keep R4's parallel 3-phase scan. Gather gets cache
// policy hints: streaming stores on `out`, streaming loads on perm, so the
// 102 MB support array stays L2-resident across its 8x reuse.
// ---------------------------------------------------------------------------

#define D 512
#define MAX_NODES 50000
#define MAX_EDGES 400000

__device__ float g_support[(size_t)MAX_NODES * D];
__device__ int   g_counts[MAX_NODES];
__device__ int   g_offsets[MAX_NODES + 1];
__device__ int   g_cursors[MAX_NODES];
__device__ int   g_blocksums[256];
__device__ int2  g_perm[MAX_EDGES];

// ========================= Prep kernels ====================================
__global__ void zero_counts_kernel(int n) {
    int i = blockIdx.x * blockDim.x + threadIdx.x;
    if (i < n) g_counts[i] = 0;
}

__global__ void hist_kernel(const int* __restrict__ rows, int E) {
    int e = blockIdx.x * blockDim.x + threadIdx.x;
    if (e < E) atomicAdd(&g_counts[rows[e]], 1);
}

// scan phase 1: per-block (512 elems) exclusive scan -> g_offsets, block sums
__global__ __launch_bounds__(512)
void scan1_kernel(int n) {
    __shared__ int ws[16];
    const int tid  = threadIdx.x;
    const int lane = tid & 31;
    const int wid  = tid >> 5;
    const int i = blockIdx.x * 512 + tid;
    const int v = (i < n) ? g_counts[i] : 0;

    int x = v;
    #pragma unroll
    for (int d = 1; d < 32; d <<= 1) {
        int y = __shfl_up_sync(0xffffffffu, x, d);
        if (lane >= d) x += y;
    }
    if (lane == 31) ws[wid] = x;
    __syncthreads();
    if (wid == 0) {
        int w = (lane < 16) ? ws[lane] : 0;
        #pragma unroll
        for (int d = 1; d < 16; d <<= 1) {
            int y = __shfl_up_sync(0xffffffffu, w, d);
            if (lane >= d) w += y;
        }
        if (lane < 16) ws[lane] = w;
    }
    __syncthreads();
    const int excl = (wid ? ws[wid - 1] : 0) + x - v;
    if (i < n) g_offsets[i] = excl;
    if (tid == 511) g_blocksums[blockIdx.x] = ws[15];
}

// scan phase 2: exclusive scan of block sums (nb <= 128), one block
__global__ __launch_bounds__(128)
void scan2_kernel(int nb) {
    __shared__ int ws[4];
    const int tid  = threadIdx.x;
    const int lane = tid & 31;
    const int wid  = tid >> 5;
    const int v = (tid < nb) ? g_blocksums[tid] : 0;
    int x = v;
    #pragma unroll
    for (int d = 1; d < 32; d <<= 1) {
        int y = __shfl_up_sync(0xffffffffu, x, d);
        if (lane >= d) x += y;
    }
    if (lane == 31) ws[wid] = x;
    __syncthreads();
    if (wid == 0 && lane < 4) {
        int w = ws[lane];
        #pragma unroll
        for (int d = 1; d < 4; d <<= 1) {
            int y = __shfl_up_sync(0x0000000fu, w, d);
            if (lane >= d) w += y;
        }
        ws[lane] = w;
    }
    __syncthreads();
    const int excl = (wid ? ws[wid - 1] : 0) + x - v;
    if (tid < nb) g_blocksums[tid] = excl;
}

// scan phase 3: add block prefix, write cursors and offsets[n]
__global__ __launch_bounds__(512)
void scan3_kernel(int n, int E) {
    const int i = blockIdx.x * 512 + threadIdx.x;
    if (i < n) {
        const int off = g_offsets[i] + g_blocksums[blockIdx.x];
        g_offsets[i] = off;
        g_cursors[i] = off;
    }
    if (i == 0) g_offsets[n] = E;
}

__global__ void place_kernel(const int* __restrict__ rows,
                             const int* __restrict__ cols,
                             const float* __restrict__ vals,
                             int E) {
    int e = blockIdx.x * blockDim.x + threadIdx.x;
    if (e >= E) return;
    int pos = atomicAdd(&g_cursors[rows[e]], 1);
    g_perm[pos] = make_int2(cols[e], __float_as_int(vals[e]));
}

// ---------------------------------------------------------------------------
// TF32 tensor-core GEMM, register-staged pipeline (R3 version, proven).
// CTA tile 128x128x16, 8 warps (4x2), warp tile 32x64, mma.m16n8k8.tf32.
// ---------------------------------------------------------------------------
#define BM 128
#define BN 128
#define BK 16
#define SSTRIDE (BM + 8)   // 136 % 32 == 8 -> conflict-free fragment LDS

__device__ __forceinline__ uint32_t f32_to_tf32(float f) {
    uint32_t r;
    asm("cvt.rna.tf32.f32 %0, %1;" : "=r"(r) : "f"(f));
    return r;
}

__global__ __launch_bounds__(256, 2)
void tf32_gemm_kernel(const float* __restrict__ A,
                      const float* __restrict__ B,
                      float* __restrict__ C,
                      int M) {
    constexpr int N = 512, K = 512;

    __shared__ uint32_t As[BK][SSTRIDE];
    __shared__ uint32_t Bs[BK][SSTRIDE];

    const int tid  = threadIdx.x;
    const int wid  = tid >> 5;
    const int lane = tid & 31;
    const int g    = lane >> 2;
    const int tg   = lane & 3;

    const int wm = (wid >> 1) * 32;
    const int wn = (wid & 1) * 64;

    const int m_base = blockIdx.y * BM;
    const int n_base = blockIdx.x * BN;

    float acc[2][8][4];
    #pragma unroll
    for (int mi = 0; mi < 2; mi++)
        #pragma unroll
        for (int ni = 0; ni < 8; ni++)
            #pragma unroll
            for (int r = 0; r < 4; r++) acc[mi][ni][r] = 0.0f;

    float4 a_stage[2], b_stage[2];

    #pragma unroll
    for (int j = 0; j < 2; j++) {
        const int f   = tid * 2 + j;
        const int row = f >> 2;
        const int kq  = (f & 3) * 4;
        a_stage[j] = make_float4(0.f, 0.f, 0.f, 0.f);
        if (m_base + row < M)
            a_stage[j] = *reinterpret_cast<const float4*>(
                             A + (size_t)(m_base + row) * K + kq);
        const int brow = f >> 5;
        const int bc4  = (f & 31) * 4;
        b_stage[j] = *reinterpret_cast<const float4*>(
                         B + (size_t)brow * N + n_base + bc4);
    }

    for (int k0 = 0; k0 < K; k0 += BK) {
        #pragma unroll
        for (int j = 0; j < 2; j++) {
            const int f   = tid * 2 + j;
            const int row = f >> 2;
            const int kq  = (f & 3) * 4;
            As[kq + 0][row] = f32_to_tf32(a_stage[j].x);
            As[kq + 1][row] = f32_to_tf32(a_stage[j].y);
            As[kq + 2][row] = f32_to_tf32(a_stage[j].z);
            As[kq + 3][row] = f32_to_tf32(a_stage[j].w);
            const int brow = f >> 5;
            const int bc4  = (f & 31) * 4;
            uint4 t;
            t.x = f32_to_tf32(b_stage[j].x);
            t.y = f32_to_tf32(b_stage[j].y);
            t.z = f32_to_tf32(b_stage[j].z);
            t.w = f32_to_tf32(b_stage[j].w);
            *reinterpret_cast<uint4*>(&Bs[brow][bc4]) = t;
        }
        __syncthreads();

        const int k1 = k0 + BK;
        if (k1 < K) {
            #pragma unroll
            for (int j = 0; j < 2; j++) {
                const int f   = tid * 2 + j;
                const int row = f >> 2;
                const int kq  = (f & 3) * 4;
                a_stage[j] = make_float4(0.f, 0.f, 0.f, 0.f);
                if (m_base + row < M)
                    a_stage[j] = *reinterpret_cast<const float4*>(
                                     A + (size_t)(m_base + row) * K + k1 + kq);
                const int brow = f >> 5;
                const int bc4  = (f & 31) * 4;
                b_stage[j] = *reinterpret_cast<const float4*>(
                                 B + (size_t)(k1 + brow) * N + n_base + bc4);
            }
        }

        #pragma unroll
        for (int ks = 0; ks < BK; ks += 8) {
            uint32_t a[2][4], b[8][2];
            #pragma unroll
            for (int mi = 0; mi < 2; mi++) {
                const int m0 = wm + mi * 16;
                a[mi][0] = As[ks + tg    ][m0 + g    ];
                a[mi][1] = As[ks + tg    ][m0 + g + 8];
                a[mi][2] = As[ks + tg + 4][m0 + g    ];
                a[mi][3] = As[ks + tg + 4][m0 + g + 8];
            }
            #pragma unroll
            for (int ni = 0; ni < 8; ni++) {
                const int n0 = wn + ni * 8;
                b[ni][0] = Bs[ks + tg    ][n0 + g];
                b[ni][1] = Bs[ks + tg + 4][n0 + g];
            }
            #pragma unroll
            for (int mi = 0; mi < 2; mi++)
                #pragma unroll
                for (int ni = 0; ni < 8; ni++) {
                    asm volatile(
                        "mma.sync.aligned.m16n8k8.row.col.f32.tf32.tf32.f32 "
                        "{%0,%1,%2,%3}, {%4,%5,%6,%7}, {%8,%9}, {%0,%1,%2,%3};"
                        : "+f"(acc[mi][ni][0]), "+f"(acc[mi][ni][1]),
                          "+f"(acc[mi][ni][2]), "+f"(acc[mi][ni][3])
                        : "r"(a[mi][0]), "r"(a[mi][1]), "r"(a[mi][2]), "r"(a[mi][3]),
                          "r"(b[ni][0]), "r"(b[ni][1]));
                }
        }
        __syncthreads();
    }

    #pragma unroll
    for (int mi = 0; mi < 2; mi++) {
        const int row0 = m_base + wm + mi * 16 + g;
        const int row1 = row0 + 8;
        #pragma unroll
        for (int ni = 0; ni < 8; ni++) {
            const int col = n_base + wn + ni * 8 + 2 * tg;
            if (row0 < M) {
                float2 v = make_float2(acc[mi][ni][0], acc[mi][ni][1]);
                *reinterpret_cast<float2*>(C + (size_t)row0 * N + col) = v;
            }
            if (row1 < M) {
                float2 v = make_float2(acc[mi][ni][2], acc[mi][ni][3]);
                *reinterpret_cast<float2*>(C + (size_t)row1 * N + col) = v;
            }
        }
    }
}

// ---------------------------------------------------------------------------
// Row-gather: 4 warps per output row (quarter-row each), 4-edge unroll.
// Cache policy: perm loads streaming (__ldcs), support loads default/
// persisting (__ldg), out stores streaming (__stcs) to keep support in L2.
// ---------------------------------------------------------------------------
__global__ __launch_bounds__(256)
void row_gather_kernel(const float* __restrict__ bias,
                       float* __restrict__ out,
                       int n_rows) {
    const int gw   = (blockIdx.x * blockDim.x + threadIdx.x) >> 5;
    const int lane = threadIdx.x & 31;
    const int row  = gw >> 2;
    const int part = gw & 3;
    if (row >= n_rows) return;

    const int s = g_offsets[row];
    const int e = g_offsets[row + 1];
    const int fo = part * 32 + lane;

    float4 acc = make_float4(0.f, 0.f, 0.f, 0.f);

    int i = s;
    for (; i + 3 < e; i += 4) {
        const int2 cv0 = __ldcs(&g_perm[i]);
        const int2 cv1 = __ldcs(&g_perm[i + 1]);
        const int2 cv2 = __ldcs(&g_perm[i + 2]);
        const int2 cv3 = __ldcs(&g_perm[i + 3]);
        const float4 m0 = __ldg(reinterpret_cast<const float4*>(
                              g_support + (size_t)cv0.x * D) + fo);
        const float4 m1 = __ldg(reinterpret_cast<const float4*>(
                              g_support + (size_t)cv1.x * D) + fo);
        const float4 m2 = __ldg(reinterpret_cast<const float4*>(
                              g_support + (size_t)cv2.x * D) + fo);
        const float4 m3 = __ldg(reinterpret_cast<const float4*>(
                              g_support + (size_t)cv3.x * D) + fo);
        const float v0 = __int_as_float(cv0.y);
        const float v1 = __int_as_float(cv1.y);
        const float v2 = __int_as_float(cv2.y);
        const float v3 = __int_as_float(cv3.y);
        acc.x += v0 * m0.x + v1 * m1.x + v2 * m2.x + v3 * m3.x;
        acc.y += v0 * m0.y + v1 * m1.y + v2 * m2.y + v3 * m3.y;
        acc.z += v0 * m0.z + v1 * m1.z + v2 * m2.z + v3 * m3.z;
        acc.w += v0 * m0.w + v1 * m1.w + v2 * m2.w + v3 * m3.w;
    }
    for (; i < e; i++) {
        const int2 cv = __ldcs(&g_perm[i]);
        const float v = __int_as_float(cv.y);
        const float4 m = __ldg(reinterpret_cast<const float4*>(
                             g_support + (size_t)cv.x * D) + fo);
        acc.x += v * m.x;
        acc.y += v * m.y;
        acc.z += v * m.z;
        acc.w += v * m.w;
    }

    const float4 b = __ldg(reinterpret_cast<const float4*>(bias) + fo);
    const float4 r = make_float4(acc.x + b.x, acc.y + b.y,
                                 acc.z + b.z, acc.w + b.w);
    __stcs(reinterpret_cast<float4*>(out + (size_t)row * D) + fo, r);
}

// ========================= Launch ==========================================
extern "C" void kernel_launch(void* const* d_in, const int* in_sizes, int n_in,
                              void* d_out, int out_size) {
    const float* x        = (const float*)d_in[0];
    const int*   adj_rows = (const int*)  d_in[1];
    const int*   adj_cols = (const int*)  d_in[2];
    const float* adj_vals = (const float*)d_in[3];
    const float* weight   = (const float*)d_in[4];
    const float* bias     = (const float*)d_in[5];
    float* out = (float*)d_out;

    const int M = in_sizes[0] / D;   // N_NODES
    const int E = in_sizes[1];       // N_EDGES

    // --- CSR prep (parallel 3-phase scan) ---
    zero_counts_kernel<<<(M + 255) / 256, 256>>>(M);
    hist_kernel<<<(E + 255) / 256, 256>>>(adj_rows, E);
    const int nb = (M + 511) / 512;
    scan1_kernel<<<nb, 512>>>(M);
    scan2_kernel<<<1, 128>>>(nb);
    scan3_kernel<<<nb, 512>>>(M, E);
    place_kernel<<<(E + 255) / 256, 256>>>(adj_rows, adj_cols, adj_vals, E);

    // --- support = x @ W (tf32 tensor cores, pipelined) ---
    {
        float* support;
        cudaGetSymbolAddress((void**)&support, g_support);
        dim3 grid(D / BN, (M + BM - 1) / BM);
        tf32_gemm_kernel<<<grid, 256>>>(x, weight, support, M);
    }

    // --- out[r] = sum val * support[col] + bias ---
    {
        int total_warps = 4 * M;
        int blocks = (total_warps + 7) / 8;
        row_gather_kernel<<<blocks, 256>>>(bias, out, M);
    }
}

// round 7
// speedup vs baseline: 1.2354x; 1.1707x over previous
#include <cuda_runtime.h>
#include <cuda_fp16.h>
#include <cstdint>

// ---------------------------------------------------------------------------
// GraphConvolution: out = SpMM(COO adj, x @ W) + bias
// Round 6: support stored as fp16 (51 MB -> fully L2-resident, gather read
// bytes halved). GEMM: mma.sync tf32 (proven). Parallel scan prep (proven).
// ---------------------------------------------------------------------------

#define D 512
#define MAX_NODES 50000
#define MAX_EDGES 400000

__device__ __half g_support[(size_t)MAX_NODES * D];   // 51.2 MB
__device__ int    g_counts[MAX_NODES];
__device__ int    g_offsets[MAX_NODES + 1];
__device__ int    g_cursors[MAX_NODES];
__device__ int    g_blocksums[256];
__device__ int2   g_perm[MAX_EDGES];

// ========================= Prep kernels ====================================
__global__ void zero_counts_kernel(int n) {
    int i = blockIdx.x * blockDim.x + threadIdx.x;
    if (i < n) g_counts[i] = 0;
}

__global__ void hist_kernel(const int* __restrict__ rows, int E) {
    int e = blockIdx.x * blockDim.x + threadIdx.x;
    if (e < E) atomicAdd(&g_counts[rows[e]], 1);
}

__global__ __launch_bounds__(512)
void scan1_kernel(int n) {
    __shared__ int ws[16];
    const int tid  = threadIdx.x;
    const int lane = tid & 31;
    const int wid  = tid >> 5;
    const int i = blockIdx.x * 512 + tid;
    const int v = (i < n) ? g_counts[i] : 0;

    int x = v;
    #pragma unroll
    for (int d = 1; d < 32; d <<= 1) {
        int y = __shfl_up_sync(0xffffffffu, x, d);
        if (lane >= d) x += y;
    }
    if (lane == 31) ws[wid] = x;
    __syncthreads();
    if (wid == 0) {
        int w = (lane < 16) ? ws[lane] : 0;
        #pragma unroll
        for (int d = 1; d < 16; d <<= 1) {
            int y = __shfl_up_sync(0xffffffffu, w, d);
            if (lane >= d) w += y;
        }
        if (lane < 16) ws[lane] = w;
    }
    __syncthreads();
    const int excl = (wid ? ws[wid - 1] : 0) + x - v;
    if (i < n) g_offsets[i] = excl;
    if (tid == 511) g_blocksums[blockIdx.x] = ws[15];
}

__global__ __launch_bounds__(128)
void scan2_kernel(int nb) {
    __shared__ int ws[4];
    const int tid  = threadIdx.x;
    const int lane = tid & 31;
    const int wid  = tid >> 5;
    const int v = (tid < nb) ? g_blocksums[tid] : 0;
    int x = v;
    #pragma unroll
    for (int d = 1; d < 32; d <<= 1) {
        int y = __shfl_up_sync(0xffffffffu, x, d);
        if (lane >= d) x += y;
    }
    if (lane == 31) ws[wid] = x;
    __syncthreads();
    if (wid == 0 && lane < 4) {
        int w = ws[lane];
        #pragma unroll
        for (int d = 1; d < 4; d <<= 1) {
            int y = __shfl_up_sync(0x0000000fu, w, d);
            if (lane >= d) w += y;
        }
        ws[lane] = w;
    }
    __syncthreads();
    const int excl = (wid ? ws[wid - 1] : 0) + x - v;
    if (tid < nb) g_blocksums[tid] = excl;
}

__global__ __launch_bounds__(512)
void scan3_kernel(int n, int E) {
    const int i = blockIdx.x * 512 + threadIdx.x;
    if (i < n) {
        const int off = g_offsets[i] + g_blocksums[blockIdx.x];
        g_offsets[i] = off;
        g_cursors[i] = off;
    }
    if (i == 0) g_offsets[n] = E;
}

__global__ void place_kernel(const int* __restrict__ rows,
                             const int* __restrict__ cols,
                             const float* __restrict__ vals,
                             int E) {
    int e = blockIdx.x * blockDim.x + threadIdx.x;
    if (e >= E) return;
    int pos = atomicAdd(&g_cursors[rows[e]], 1);
    g_perm[pos] = make_int2(cols[e], __float_as_int(vals[e]));
}

// ---------------------------------------------------------------------------
// TF32 tensor-core GEMM -> fp16 output.
// CTA tile 128x128x16, 8 warps (4x2), warp tile 32x64, mma.m16n8k8.tf32.
// ---------------------------------------------------------------------------
#define BM 128
#define BN 128
#define BK 16
#define SSTRIDE (BM + 8)

__device__ __forceinline__ uint32_t f32_to_tf32(float f) {
    uint32_t r;
    asm("cvt.rna.tf32.f32 %0, %1;" : "=r"(r) : "f"(f));
    return r;
}

__global__ __launch_bounds__(256, 2)
void tf32_gemm_kernel(const float* __restrict__ A,
                      const float* __restrict__ B,
                      __half* __restrict__ C,     // fp16 output
                      int M) {
    constexpr int N = 512, K = 512;

    __shared__ uint32_t As[BK][SSTRIDE];
    __shared__ uint32_t Bs[BK][SSTRIDE];

    const int tid  = threadIdx.x;
    const int wid  = tid >> 5;
    const int lane = tid & 31;
    const int g    = lane >> 2;
    const int tg   = lane & 3;

    const int wm = (wid >> 1) * 32;
    const int wn = (wid & 1) * 64;

    const int m_base = blockIdx.y * BM;
    const int n_base = blockIdx.x * BN;

    float acc[2][8][4];
    #pragma unroll
    for (int mi = 0; mi < 2; mi++)
        #pragma unroll
        for (int ni = 0; ni < 8; ni++)
            #pragma unroll
            for (int r = 0; r < 4; r++) acc[mi][ni][r] = 0.0f;

    float4 a_stage[2], b_stage[2];

    #pragma unroll
    for (int j = 0; j < 2; j++) {
        const int f   = tid * 2 + j;
        const int row = f >> 2;
        const int kq  = (f & 3) * 4;
        a_stage[j] = make_float4(0.f, 0.f, 0.f, 0.f);
        if (m_base + row < M)
            a_stage[j] = *reinterpret_cast<const float4*>(
                             A + (size_t)(m_base + row) * K + kq);
        const int brow = f >> 5;
        const int bc4  = (f & 31) * 4;
        b_stage[j] = *reinterpret_cast<const float4*>(
                         B + (size_t)brow * N + n_base + bc4);
    }

    for (int k0 = 0; k0 < K; k0 += BK) {
        #pragma unroll
        for (int j = 0; j < 2; j++) {
            const int f   = tid * 2 + j;
            const int row = f >> 2;
            const int kq  = (f & 3) * 4;
            As[kq + 0][row] = f32_to_tf32(a_stage[j].x);
            As[kq + 1][row] = f32_to_tf32(a_stage[j].y);
            As[kq + 2][row] = f32_to_tf32(a_stage[j].z);
            As[kq + 3][row] = f32_to_tf32(a_stage[j].w);
            const int brow = f >> 5;
            const int bc4  = (f & 31) * 4;
            uint4 t;
            t.x = f32_to_tf32(b_stage[j].x);
            t.y = f32_to_tf32(b_stage[j].y);
            t.z = f32_to_tf32(b_stage[j].z);
            t.w = f32_to_tf32(b_stage[j].w);
            *reinterpret_cast<uint4*>(&Bs[brow][bc4]) = t;
        }
        __syncthreads();

        const int k1 = k0 + BK;
        if (k1 < K) {
            #pragma unroll
            for (int j = 0; j < 2; j++) {
                const int f   = tid * 2 + j;
                const int row = f >> 2;
                const int kq  = (f & 3) * 4;
                a_stage[j] = make_float4(0.f, 0.f, 0.f, 0.f);
                if (m_base + row < M)
                    a_stage[j] = *reinterpret_cast<const float4*>(
                                     A + (size_t)(m_base + row) * K + k1 + kq);
                const int brow = f >> 5;
                const int bc4  = (f & 31) * 4;
                b_stage[j] = *reinterpret_cast<const float4*>(
                                 B + (size_t)(k1 + brow) * N + n_base + bc4);
            }
        }

        #pragma unroll
        for (int ks = 0; ks < BK; ks += 8) {
            uint32_t a[2][4], b[8][2];
            #pragma unroll
            for (int mi = 0; mi < 2; mi++) {
                const int m0 = wm + mi * 16;
                a[mi][0] = As[ks + tg    ][m0 + g    ];
                a[mi][1] = As[ks + tg    ][m0 + g + 8];
                a[mi][2] = As[ks + tg + 4][m0 + g    ];
                a[mi][3] = As[ks + tg + 4][m0 + g + 8];
            }
            #pragma unroll
            for (int ni = 0; ni < 8; ni++) {
                const int n0 = wn + ni * 8;
                b[ni][0] = Bs[ks + tg    ][n0 + g];
                b[ni][1] = Bs[ks + tg + 4][n0 + g];
            }
            #pragma unroll
            for (int mi = 0; mi < 2; mi++)
                #pragma unroll
                for (int ni = 0; ni < 8; ni++) {
                    asm volatile(
                        "mma.sync.aligned.m16n8k8.row.col.f32.tf32.tf32.f32 "
                        "{%0,%1,%2,%3}, {%4,%5,%6,%7}, {%8,%9}, {%0,%1,%2,%3};"
                        : "+f"(acc[mi][ni][0]), "+f"(acc[mi][ni][1]),
                          "+f"(acc[mi][ni][2]), "+f"(acc[mi][ni][3])
                        : "r"(a[mi][0]), "r"(a[mi][1]), "r"(a[mi][2]), "r"(a[mi][3]),
                          "r"(b[ni][0]), "r"(b[ni][1]));
                }
        }
        __syncthreads();
    }

    // ---- epilogue: convert to fp16, store half2 per (row, ni) ----
    #pragma unroll
    for (int mi = 0; mi < 2; mi++) {
        const int row0 = m_base + wm + mi * 16 + g;
        const int row1 = row0 + 8;
        #pragma unroll
        for (int ni = 0; ni < 8; ni++) {
            const int col = n_base + wn + ni * 8 + 2 * tg;
            if (row0 < M) {
                __half2 h = __floats2half2_rn(acc[mi][ni][0], acc[mi][ni][1]);
                *reinterpret_cast<__half2*>(C + (size_t)row0 * N + col) = h;
            }
            if (row1 < M) {
                __half2 h = __floats2half2_rn(acc[mi][ni][2], acc[mi][ni][3]);
                *reinterpret_cast<__half2*>(C + (size_t)row1 * N + col) = h;
            }
        }
    }
}

// ---------------------------------------------------------------------------
// Row-gather (fp16 support): 4 warps per output row; each lane owns 4 dims
// (one uint2 = 4 halves per edge). fp32 accumulate, fp32 out store.
// ---------------------------------------------------------------------------
__global__ __launch_bounds__(256)
void row_gather_kernel(const float* __restrict__ bias,
                       float* __restrict__ out,
                       int n_rows) {
    const int gw   = (blockIdx.x * blockDim.x + threadIdx.x) >> 5;
    const int lane = threadIdx.x & 31;
    const int row  = gw >> 2;
    const int part = gw & 3;
    if (row >= n_rows) return;

    const int s = g_offsets[row];
    const int e = g_offsets[row + 1];
    const int fo = part * 32 + lane;   // uint2 index (4 halves), 0..127

    float4 acc = make_float4(0.f, 0.f, 0.f, 0.f);

    int i = s;
    for (; i + 3 < e; i += 4) {
        const int2 cv0 = __ldcs(&g_perm[i]);
        const int2 cv1 = __ldcs(&g_perm[i + 1]);
        const int2 cv2 = __ldcs(&g_perm[i + 2]);
        const int2 cv3 = __ldcs(&g_perm[i + 3]);
        const uint2 m0 = __ldg(reinterpret_cast<const uint2*>(
                             g_support + (size_t)cv0.x * D) + fo);
        const uint2 m1 = __ldg(reinterpret_cast<const uint2*>(
                             g_support + (size_t)cv1.x * D) + fo);
        const uint2 m2 = __ldg(reinterpret_cast<const uint2*>(
                             g_support + (size_t)cv2.x * D) + fo);
        const uint2 m3 = __ldg(reinterpret_cast<const uint2*>(
                             g_support + (size_t)cv3.x * D) + fo);
        const float v0 = __int_as_float(cv0.y);
        const float v1 = __int_as_float(cv1.y);
        const float v2 = __int_as_float(cv2.y);
        const float v3 = __int_as_float(cv3.y);

        float2 a0 = __half22float2(*reinterpret_cast<const __half2*>(&m0.x));
        float2 b0 = __half22float2(*reinterpret_cast<const __half2*>(&m0.y));
        float2 a1 = __half22float2(*reinterpret_cast<const __half2*>(&m1.x));
        float2 b1 = __half22float2(*reinterpret_cast<const __half2*>(&m1.y));
        float2 a2 = __half22float2(*reinterpret_cast<const __half2*>(&m2.x));
        float2 b2 = __half22float2(*reinterpret_cast<const __half2*>(&m2.y));
        float2 a3 = __half22float2(*reinterpret_cast<const __half2*>(&m3.x));
        float2 b3 = __half22float2(*reinterpret_cast<const __half2*>(&m3.y));

        acc.x += v0 * a0.x + v1 * a1.x + v2 * a2.x + v3 * a3.x;
        acc.y += v0 * a0.y + v1 * a1.y + v2 * a2.y + v3 * a3.y;
        acc.z += v0 * b0.x + v1 * b1.x + v2 * b2.x + v3 * b3.x;
        acc.w += v0 * b0.y + v1 * b1.y + v2 * b2.y + v3 * b3.y;
    }
    for (; i < e; i++) {
        const int2 cv = __ldcs(&g_perm[i]);
        const float v = __int_as_float(cv.y);
        const uint2 m = __ldg(reinterpret_cast<const uint2*>(
                            g_support + (size_t)cv.x * D) + fo);
        float2 a = __half22float2(*reinterpret_cast<const __half2*>(&m.x));
        float2 b = __half22float2(*reinterpret_cast<const __half2*>(&m.y));
        acc.x += v * a.x;
        acc.y += v * a.y;
        acc.z += v * b.x;
        acc.w += v * b.y;
    }

    const float4 b = __ldg(reinterpret_cast<const float4*>(bias) + fo);
    const float4 r = make_float4(acc.x + b.x, acc.y + b.y,
                                 acc.z + b.z, acc.w + b.w);
    __stcs(reinterpret_cast<float4*>(out + (size_t)row * D) + fo, r);
}

// ========================= Launch ==========================================
extern "C" void kernel_launch(void* const* d_in, const int* in_sizes, int n_in,
                              void* d_out, int out_size) {
    const float* x        = (const float*)d_in[0];
    const int*   adj_rows = (const int*)  d_in[1];
    const int*   adj_cols = (const int*)  d_in[2];
    const float* adj_vals = (const float*)d_in[3];
    const float* weight   = (const float*)d_in[4];
    const float* bias     = (const float*)d_in[5];
    float* out = (float*)d_out;

    const int M = in_sizes[0] / D;   // N_NODES
    const int E = in_sizes[1];       // N_EDGES

    // --- CSR prep (parallel 3-phase scan) ---
    zero_counts_kernel<<<(M + 255) / 256, 256>>>(M);
    hist_kernel<<<(E + 255) / 256, 256>>>(adj_rows, E);
    const int nb = (M + 511) / 512;
    scan1_kernel<<<nb, 512>>>(M);
    scan2_kernel<<<1, 128>>>(nb);
    scan3_kernel<<<nb, 512>>>(M, E);
    place_kernel<<<(E + 255) / 256, 256>>>(adj_rows, adj_cols, adj_vals, E);

    // --- support = x @ W (tf32 tensor cores, fp16 output) ---
    {
        __half* support;
        cudaGetSymbolAddress((void**)&support, g_support);
        dim3 grid(D / BN, (M + BM - 1) / BM);
        tf32_gemm_kernel<<<grid, 256>>>(x, weight, support, M);
    }

    // --- out[r] = sum val * support[col] + bias ---
    {
        int total_warps = 4 * M;
        int blocks = (total_warps + 7) / 8;
        row_gather_kernel<<<blocks, 256>>>(bias, out, M);
    }
}

// round 8
// speedup vs baseline: 1.5233x; 1.2330x over previous
#include <cuda_runtime.h>
#include <cuda_fp16.h>
#include <cstdint>

// ---------------------------------------------------------------------------
// GraphConvolution: out = SpMM(COO adj, x @ W) + bias
// Round 7: GEMM operands fp16 (mma.m16n8k16.f16, fp32 accum) -> 2x tensor
// throughput vs tf32. Support stays fp16 (L2-resident). Prep/gather proven.
// ---------------------------------------------------------------------------

#define D 512
#define MAX_NODES 50000
#define MAX_EDGES 400000

__device__ __half g_support[(size_t)MAX_NODES * D];   // 51.2 MB
__device__ int    g_counts[MAX_NODES];
__device__ int    g_offsets[MAX_NODES + 1];
__device__ int    g_cursors[MAX_NODES];
__device__ int    g_blocksums[256];
__device__ int2   g_perm[MAX_EDGES];

// ========================= Prep kernels ====================================
__global__ void zero_counts_kernel(int n) {
    int i = blockIdx.x * blockDim.x + threadIdx.x;
    if (i < n) g_counts[i] = 0;
}

__global__ void hist_kernel(const int* __restrict__ rows, int E) {
    int e = blockIdx.x * blockDim.x + threadIdx.x;
    if (e < E) atomicAdd(&g_counts[rows[e]], 1);
}

__global__ __launch_bounds__(512)
void scan1_kernel(int n) {
    __shared__ int ws[16];
    const int tid  = threadIdx.x;
    const int lane = tid & 31;
    const int wid  = tid >> 5;
    const int i = blockIdx.x * 512 + tid;
    const int v = (i < n) ? g_counts[i] : 0;

    int x = v;
    #pragma unroll
    for (int d = 1; d < 32; d <<= 1) {
        int y = __shfl_up_sync(0xffffffffu, x, d);
        if (lane >= d) x += y;
    }
    if (lane == 31) ws[wid] = x;
    __syncthreads();
    if (wid == 0) {
        int w = (lane < 16) ? ws[lane] : 0;
        #pragma unroll
        for (int d = 1; d < 16; d <<= 1) {
            int y = __shfl_up_sync(0xffffffffu, w, d);
            if (lane >= d) w += y;
        }
        if (lane < 16) ws[lane] = w;
    }
    __syncthreads();
    const int excl = (wid ? ws[wid - 1] : 0) + x - v;
    if (i < n) g_offsets[i] = excl;
    if (tid == 511) g_blocksums[blockIdx.x] = ws[15];
}

__global__ __launch_bounds__(128)
void scan2_kernel(int nb) {
    __shared__ int ws[4];
    const int tid  = threadIdx.x;
    const int lane = tid & 31;
    const int wid  = tid >> 5;
    const int v = (tid < nb) ? g_blocksums[tid] : 0;
    int x = v;
    #pragma unroll
    for (int d = 1; d < 32; d <<= 1) {
        int y = __shfl_up_sync(0xffffffffu, x, d);
        if (lane >= d) x += y;
    }
    if (lane == 31) ws[wid] = x;
    __syncthreads();
    if (wid == 0 && lane < 4) {
        int w = ws[lane];
        #pragma unroll
        for (int d = 1; d < 4; d <<= 1) {
            int y = __shfl_up_sync(0x0000000fu, w, d);
            if (lane >= d) w += y;
        }
        ws[lane] = w;
    }
    __syncthreads();
    const int excl = (wid ? ws[wid - 1] : 0) + x - v;
    if (tid < nb) g_blocksums[tid] = excl;
}

__global__ __launch_bounds__(512)
void scan3_kernel(int n, int E) {
    const int i = blockIdx.x * 512 + threadIdx.x;
    if (i < n) {
        const int off = g_offsets[i] + g_blocksums[blockIdx.x];
        g_offsets[i] = off;
        g_cursors[i] = off;
    }
    if (i == 0) g_offsets[n] = E;
}

__global__ void place_kernel(const int* __restrict__ rows,
                             const int* __restrict__ cols,
                             const float* __restrict__ vals,
                             int E) {
    int e = blockIdx.x * blockDim.x + threadIdx.x;
    if (e >= E) return;
    int pos = atomicAdd(&g_cursors[rows[e]], 1);
    g_perm[pos] = make_int2(cols[e], __float_as_int(vals[e]));
}

// ---------------------------------------------------------------------------
// FP16 tensor-core GEMM (fp32 accum) -> fp16 output.
// CTA tile 128x128x32, 8 warps (4x2), warp tile 32x64, mma.m16n8k16.f16.
// Smem: As/Bs hold k-PAIRS as packed half2 (uint32), k-major, stride 136
// (136 % 32 == 8 -> conflict-free fragment LDS, same pattern as tf32 ver).
// ---------------------------------------------------------------------------
#define BM 128
#define BN 128
#define BK 32               // real k per tile
#define KP (BK / 2)         // 16 k-pairs
#define SSTRIDE (BM + 8)    // 136

__device__ __forceinline__ uint32_t pack_h2(float a, float b) {
    __half2 h = __floats2half2_rn(a, b);
    return *reinterpret_cast<uint32_t*>(&h);
}

__global__ __launch_bounds__(256, 2)
void f16_gemm_kernel(const float* __restrict__ A,
                     const float* __restrict__ B,
                     __half* __restrict__ C,
                     int M) {
    constexpr int N = 512, K = 512;

    __shared__ uint32_t As[KP][SSTRIDE];   // As[kp][m] = halves (2kp, 2kp+1) of row m
    __shared__ uint32_t Bs[KP][SSTRIDE];   // Bs[kp][n] = halves (2kp, 2kp+1) of col n

    const int tid  = threadIdx.x;
    const int wid  = tid >> 5;
    const int lane = tid & 31;
    const int g    = lane >> 2;
    const int tg   = lane & 3;

    const int wm = (wid >> 1) * 32;
    const int wn = (wid & 1) * 64;

    const int m_base = blockIdx.y * BM;
    const int n_base = blockIdx.x * BN;

    float acc[2][8][4];
    #pragma unroll
    for (int mi = 0; mi < 2; mi++)
        #pragma unroll
        for (int ni = 0; ni < 8; ni++)
            #pragma unroll
            for (int r = 0; r < 4; r++) acc[mi][ni][r] = 0.0f;

    // staging: A 4 float4 (row, 4k each), B 2 pair-loads x 2 float4
    float4 a_stage[4];
    float4 b_stage[2][2];

    auto load_tile = [&](int k0) {
        #pragma unroll
        for (int j = 0; j < 4; j++) {
            const int f   = tid * 4 + j;          // 0..1023
            const int row = f >> 3;               // 0..127
            const int kq  = (f & 7) * 4;          // 0..28
            a_stage[j] = make_float4(0.f, 0.f, 0.f, 0.f);
            if (m_base + row < M)
                a_stage[j] = *reinterpret_cast<const float4*>(
                                 A + (size_t)(m_base + row) * K + k0 + kq);
        }
        #pragma unroll
        for (int j = 0; j < 2; j++) {
            const int p  = tid * 2 + j;           // 0..511
            const int kp = p >> 5;                // 0..15
            const int nq = (p & 31) * 4;          // 0..124
            b_stage[j][0] = *reinterpret_cast<const float4*>(
                                B + (size_t)(k0 + 2 * kp) * N + n_base + nq);
            b_stage[j][1] = *reinterpret_cast<const float4*>(
                                B + (size_t)(k0 + 2 * kp + 1) * N + n_base + nq);
        }
    };

    auto commit_tile = [&]() {
        #pragma unroll
        for (int j = 0; j < 4; j++) {
            const int f   = tid * 4 + j;
            const int row = f >> 3;
            const int kq  = (f & 7) * 4;
            const int kp  = kq >> 1;              // 0,2,...,14
            As[kp    ][row] = pack_h2(a_stage[j].x, a_stage[j].y);
            As[kp + 1][row] = pack_h2(a_stage[j].z, a_stage[j].w);
        }
        #pragma unroll
        for (int j = 0; j < 2; j++) {
            const int p  = tid * 2 + j;
            const int kp = p >> 5;
            const int nq = (p & 31) * 4;
            uint4 t;
            t.x = pack_h2(b_stage[j][0].x, b_stage[j][1].x);
            t.y = pack_h2(b_stage[j][0].y, b_stage[j][1].y);
            t.z = pack_h2(b_stage[j][0].z, b_stage[j][1].z);
            t.w = pack_h2(b_stage[j][0].w, b_stage[j][1].w);
            *reinterpret_cast<uint4*>(&Bs[kp][nq]) = t;
        }
    };

    load_tile(0);

    for (int k0 = 0; k0 < K; k0 += BK) {
        commit_tile();
        __syncthreads();

        if (k0 + BK < K) load_tile(k0 + BK);

        // 2 mma k-steps of 16 real k (8 k-pairs each)
        #pragma unroll
        for (int ks = 0; ks < KP; ks += 8) {
            uint32_t a[2][4], b[8][2];
            #pragma unroll
            for (int mi = 0; mi < 2; mi++) {
                const int m0 = wm + mi * 16;
                a[mi][0] = As[ks + tg    ][m0 + g    ];
                a[mi][1] = As[ks + tg    ][m0 + g + 8];
                a[mi][2] = As[ks + tg + 4][m0 + g    ];
                a[mi][3] = As[ks + tg + 4][m0 + g + 8];
            }
            #pragma unroll
            for (int ni = 0; ni < 8; ni++) {
                const int n0 = wn + ni * 8;
                b[ni][0] = Bs[ks + tg    ][n0 + g];
                b[ni][1] = Bs[ks + tg + 4][n0 + g];
            }
            #pragma unroll
            for (int mi = 0; mi < 2; mi++)
                #pragma unroll
                for (int ni = 0; ni < 8; ni++) {
                    asm volatile(
                        "mma.sync.aligned.m16n8k16.row.col.f32.f16.f16.f32 "
                        "{%0,%1,%2,%3}, {%4,%5,%6,%7}, {%8,%9}, {%0,%1,%2,%3};"
                        : "+f"(acc[mi][ni][0]), "+f"(acc[mi][ni][1]),
                          "+f"(acc[mi][ni][2]), "+f"(acc[mi][ni][3])
                        : "r"(a[mi][0]), "r"(a[mi][1]), "r"(a[mi][2]), "r"(a[mi][3]),
                          "r"(b[ni][0]), "r"(b[ni][1]));
                }
        }
        __syncthreads();
    }

    // ---- epilogue: convert to fp16, store half2 per (row, ni) ----
    #pragma unroll
    for (int mi = 0; mi < 2; mi++) {
        const int row0 = m_base + wm + mi * 16 + g;
        const int row1 = row0 + 8;
        #pragma unroll
        for (int ni = 0; ni < 8; ni++) {
            const int col = n_base + wn + ni * 8 + 2 * tg;
            if (row0 < M) {
                __half2 h = __floats2half2_rn(acc[mi][ni][0], acc[mi][ni][1]);
                *reinterpret_cast<__half2*>(C + (size_t)row0 * N + col) = h;
            }
            if (row1 < M) {
                __half2 h = __floats2half2_rn(acc[mi][ni][2], acc[mi][ni][3]);
                *reinterpret_cast<__half2*>(C + (size_t)row1 * N + col) = h;
            }
        }
    }
}

// ---------------------------------------------------------------------------
// Row-gather (fp16 support): 4 warps per output row; each lane owns 4 dims.
// ---------------------------------------------------------------------------
__global__ __launch_bounds__(256)
void row_gather_kernel(const float* __restrict__ bias,
                       float* __restrict__ out,
                       int n_rows) {
    const int gw   = (blockIdx.x * blockDim.x + threadIdx.x) >> 5;
    const int lane = threadIdx.x & 31;
    const int row  = gw >> 2;
    const int part = gw & 3;
    if (row >= n_rows) return;

    const int s = g_offsets[row];
    const int e = g_offsets[row + 1];
    const int fo = part * 32 + lane;

    float4 acc = make_float4(0.f, 0.f, 0.f, 0.f);

    int i = s;
    for (; i + 3 < e; i += 4) {
        const int2 cv0 = __ldcs(&g_perm[i]);
        const int2 cv1 = __ldcs(&g_perm[i + 1]);
        const int2 cv2 = __ldcs(&g_perm[i + 2]);
        const int2 cv3 = __ldcs(&g_perm[i + 3]);
        const uint2 m0 = __ldg(reinterpret_cast<const uint2*>(
                             g_support + (size_t)cv0.x * D) + fo);
        const uint2 m1 = __ldg(reinterpret_cast<const uint2*>(
                             g_support + (size_t)cv1.x * D) + fo);
        const uint2 m2 = __ldg(reinterpret_cast<const uint2*>(
                             g_support + (size_t)cv2.x * D) + fo);
        const uint2 m3 = __ldg(reinterpret_cast<const uint2*>(
                             g_support + (size_t)cv3.x * D) + fo);
        const float v0 = __int_as_float(cv0.y);
        const float v1 = __int_as_float(cv1.y);
        const float v2 = __int_as_float(cv2.y);
        const float v3 = __int_as_float(cv3.y);

        float2 a0 = __half22float2(*reinterpret_cast<const __half2*>(&m0.x));
        float2 b0 = __half22float2(*reinterpret_cast<const __half2*>(&m0.y));
        float2 a1 = __half22float2(*reinterpret_cast<const __half2*>(&m1.x));
        float2 b1 = __half22float2(*reinterpret_cast<const __half2*>(&m1.y));
        float2 a2 = __half22float2(*reinterpret_cast<const __half2*>(&m2.x));
        float2 b2 = __half22float2(*reinterpret_cast<const __half2*>(&m2.y));
        float2 a3 = __half22float2(*reinterpret_cast<const __half2*>(&m3.x));
        float2 b3 = __half22float2(*reinterpret_cast<const __half2*>(&m3.y));

        acc.x += v0 * a0.x + v1 * a1.x + v2 * a2.x + v3 * a3.x;
        acc.y += v0 * a0.y + v1 * a1.y + v2 * a2.y + v3 * a3.y;
        acc.z += v0 * b0.x + v1 * b1.x + v2 * b2.x + v3 * b3.x;
        acc.w += v0 * b0.y + v1 * b1.y + v2 * b2.y + v3 * b3.y;
    }
    for (; i < e; i++) {
        const int2 cv = __ldcs(&g_perm[i]);
        const float v = __int_as_float(cv.y);
        const uint2 m = __ldg(reinterpret_cast<const uint2*>(
                            g_support + (size_t)cv.x * D) + fo);
        float2 a = __half22float2(*reinterpret_cast<const __half2*>(&m.x));
        float2 b = __half22float2(*reinterpret_cast<const __half2*>(&m.y));
        acc.x += v * a.x;
        acc.y += v * a.y;
        acc.z += v * b.x;
        acc.w += v * b.y;
    }

    const float4 b = __ldg(reinterpret_cast<const float4*>(bias) + fo);
    const float4 r = make_float4(acc.x + b.x, acc.y + b.y,
                                 acc.z + b.z, acc.w + b.w);
    __stcs(reinterpret_cast<float4*>(out + (size_t)row * D) + fo, r);
}

// ========================= Launch ==========================================
extern "C" void kernel_launch(void* const* d_in, const int* in_sizes, int n_in,
                              void* d_out, int out_size) {
    const float* x        = (const float*)d_in[0];
    const int*   adj_rows = (const int*)  d_in[1];
    const int*   adj_cols = (const int*)  d_in[2];
    const float* adj_vals = (const float*)d_in[3];
    const float* weight   = (const float*)d_in[4];
    const float* bias     = (const float*)d_in[5];
    float* out = (float*)d_out;

    const int M = in_sizes[0] / D;   // N_NODES
    const int E = in_sizes[1];       // N_EDGES

    // --- CSR prep (parallel 3-phase scan) ---
    zero_counts_kernel<<<(M + 255) / 256, 256>>>(M);
    hist_kernel<<<(E + 255) / 256, 256>>>(adj_rows, E);
    const int nb = (M + 511) / 512;
    scan1_kernel<<<nb, 512>>>(M);
    scan2_kernel<<<1, 128>>>(nb);
    scan3_kernel<<<nb, 512>>>(M, E);
    place_kernel<<<(E + 255) / 256, 256>>>(adj_rows, adj_cols, adj_vals, E);

    // --- support = x @ W (fp16 tensor cores, fp32 accum, fp16 output) ---
    {
        __half* support;
        cudaGetSymbolAddress((void**)&support, g_support);
        dim3 grid(D / BN, (M + BM - 1) / BM);
        f16_gemm_kernel<<<grid, 256>>>(x, weight, support, M);
    }

    // --- out[r] = sum val * support[col] + bias ---
    {
        int total_warps = 4 * M;
        int blocks = (total_warps + 7) / 8;
        row_gather_kernel<<<blocks, 256>>>(bias, out, M);
    }
}

// round 9
// speedup vs baseline: 1.6241x; 1.0661x over previous
#include <cuda_runtime.h>
#include <cuda_fp16.h>
#include <cstdint>

// ---------------------------------------------------------------------------
// GraphConvolution: out = SpMM(COO adj, x @ W) + bias
// Round 8: CSR-prep chain forked onto a second stream so it overlaps the
// fp16 GEMM (they are data-independent; only the gather joins them).
// GEMM (mma.m16n8k16.f16) and gather bodies unchanged from R7 (proven).
// ---------------------------------------------------------------------------

#define D 512
#define MAX_NODES 50000
#define MAX_EDGES 400000

__device__ __half g_support[(size_t)MAX_NODES * D];   // 51.2 MB
__device__ int    g_counts[MAX_NODES];
__device__ int    g_offsets[MAX_NODES + 1];
__device__ int    g_cursors[MAX_NODES];
__device__ int    g_blocksums[256];
__device__ int2   g_perm[MAX_EDGES];

// Host-side fork/join resources, created once at program load (NOT during
// graph capture; no device memory involved).
struct ForkJoin {
    cudaStream_t side;
    cudaEvent_t  fork_ev, join_ev;
    ForkJoin() {
        cudaStreamCreateWithFlags(&side, cudaStreamNonBlocking);
        cudaEventCreateWithFlags(&fork_ev, cudaEventDisableTiming);
        cudaEventCreateWithFlags(&join_ev, cudaEventDisableTiming);
    }
};
static ForkJoin g_fj;

// ========================= Prep kernels ====================================
__global__ void zero_counts_kernel(int n) {
    int i = blockIdx.x * blockDim.x + threadIdx.x;
    if (i < n) g_counts[i] = 0;
}

__global__ void hist_kernel(const int* __restrict__ rows, int E) {
    int e = blockIdx.x * blockDim.x + threadIdx.x;
    if (e < E) atomicAdd(&g_counts[rows[e]], 1);
}

__global__ __launch_bounds__(512)
void scan1_kernel(int n) {
    __shared__ int ws[16];
    const int tid  = threadIdx.x;
    const int lane = tid & 31;
    const int wid  = tid >> 5;
    const int i = blockIdx.x * 512 + tid;
    const int v = (i < n) ? g_counts[i] : 0;

    int x = v;
    #pragma unroll
    for (int d = 1; d < 32; d <<= 1) {
        int y = __shfl_up_sync(0xffffffffu, x, d);
        if (lane >= d) x += y;
    }
    if (lane == 31) ws[wid] = x;
    __syncthreads();
    if (wid == 0) {
        int w = (lane < 16) ? ws[lane] : 0;
        #pragma unroll
        for (int d = 1; d < 16; d <<= 1) {
            int y = __shfl_up_sync(0xffffffffu, w, d);
            if (lane >= d) w += y;
        }
        if (lane < 16) ws[lane] = w;
    }
    __syncthreads();
    const int excl = (wid ? ws[wid - 1] : 0) + x - v;
    if (i < n) g_offsets[i] = excl;
    if (tid == 511) g_blocksums[blockIdx.x] = ws[15];
}

__global__ __launch_bounds__(128)
void scan2_kernel(int nb) {
    __shared__ int ws[4];
    const int tid  = threadIdx.x;
    const int lane = tid & 31;
    const int wid  = tid >> 5;
    const int v = (tid < nb) ? g_blocksums[tid] : 0;
    int x = v;
    #pragma unroll
    for (int d = 1; d < 32; d <<= 1) {
        int y = __shfl_up_sync(0xffffffffu, x, d);
        if (lane >= d) x += y;
    }
    if (lane == 31) ws[wid] = x;
    __syncthreads();
    if (wid == 0 && lane < 4) {
        int w = ws[lane];
        #pragma unroll
        for (int d = 1; d < 4; d <<= 1) {
            int y = __shfl_up_sync(0x0000000fu, w, d);
            if (lane >= d) w += y;
        }
        ws[lane] = w;
    }
    __syncthreads();
    const int excl = (wid ? ws[wid - 1] : 0) + x - v;
    if (tid < nb) g_blocksums[tid] = excl;
}

__global__ __launch_bounds__(512)
void scan3_kernel(int n, int E) {
    const int i = blockIdx.x * 512 + threadIdx.x;
    if (i < n) {
        const int off = g_offsets[i] + g_blocksums[blockIdx.x];
        g_offsets[i] = off;
        g_cursors[i] = off;
    }
    if (i == 0) g_offsets[n] = E;
}

__global__ void place_kernel(const int* __restrict__ rows,
                             const int* __restrict__ cols,
                             const float* __restrict__ vals,
                             int E) {
    int e = blockIdx.x * blockDim.x + threadIdx.x;
    if (e >= E) return;
    int pos = atomicAdd(&g_cursors[rows[e]], 1);
    g_perm[pos] = make_int2(cols[e], __float_as_int(vals[e]));
}

// ---------------------------------------------------------------------------
// FP16 tensor-core GEMM (fp32 accum) -> fp16 output.  (R7, proven)
// CTA tile 128x128x32, 8 warps (4x2), warp tile 32x64, mma.m16n8k16.f16.
// ---------------------------------------------------------------------------
#define BM 128
#define BN 128
#define BK 32
#define KP (BK / 2)
#define SSTRIDE (BM + 8)

__device__ __forceinline__ uint32_t pack_h2(float a, float b) {
    __half2 h = __floats2half2_rn(a, b);
    return *reinterpret_cast<uint32_t*>(&h);
}

__global__ __launch_bounds__(256, 2)
void f16_gemm_kernel(const float* __restrict__ A,
                     const float* __restrict__ B,
                     __half* __restrict__ C,
                     int M) {
    constexpr int N = 512, K = 512;

    __shared__ uint32_t As[KP][SSTRIDE];
    __shared__ uint32_t Bs[KP][SSTRIDE];

    const int tid  = threadIdx.x;
    const int wid  = tid >> 5;
    const int lane = tid & 31;
    const int g    = lane >> 2;
    const int tg   = lane & 3;

    const int wm = (wid >> 1) * 32;
    const int wn = (wid & 1) * 64;

    const int m_base = blockIdx.y * BM;
    const int n_base = blockIdx.x * BN;

    float acc[2][8][4];
    #pragma unroll
    for (int mi = 0; mi < 2; mi++)
        #pragma unroll
        for (int ni = 0; ni < 8; ni++)
            #pragma unroll
            for (int r = 0; r < 4; r++) acc[mi][ni][r] = 0.0f;

    float4 a_stage[4];
    float4 b_stage[2][2];

    auto load_tile = [&](int k0) {
        #pragma unroll
        for (int j = 0; j < 4; j++) {
            const int f   = tid * 4 + j;
            const int row = f >> 3;
            const int kq  = (f & 7) * 4;
            a_stage[j] = make_float4(0.f, 0.f, 0.f, 0.f);
            if (m_base + row < M)
                a_stage[j] = *reinterpret_cast<const float4*>(
                                 A + (size_t)(m_base + row) * K + k0 + kq);
        }
        #pragma unroll
        for (int j = 0; j < 2; j++) {
            const int p  = tid * 2 + j;
            const int kp = p >> 5;
            const int nq = (p & 31) * 4;
            b_stage[j][0] = *reinterpret_cast<const float4*>(
                                B + (size_t)(k0 + 2 * kp) * N + n_base + nq);
            b_stage[j][1] = *reinterpret_cast<const float4*>(
                                B + (size_t)(k0 + 2 * kp + 1) * N + n_base + nq);
        }
    };

    auto commit_tile = [&]() {
        #pragma unroll
        for (int j = 0; j < 4; j++) {
            const int f   = tid * 4 + j;
            const int row = f >> 3;
            const int kq  = (f & 7) * 4;
            const int kp  = kq >> 1;
            As[kp    ][row] = pack_h2(a_stage[j].x, a_stage[j].y);
            As[kp + 1][row] = pack_h2(a_stage[j].z, a_stage[j].w);
        }
        #pragma unroll
        for (int j = 0; j < 2; j++) {
            const int p  = tid * 2 + j;
            const int kp = p >> 5;
            const int nq = (p & 31) * 4;
            uint4 t;
            t.x = pack_h2(b_stage[j][0].x, b_stage[j][1].x);
            t.y = pack_h2(b_stage[j][0].y, b_stage[j][1].y);
            t.z = pack_h2(b_stage[j][0].z, b_stage[j][1].z);
            t.w = pack_h2(b_stage[j][0].w, b_stage[j][1].w);
            *reinterpret_cast<uint4*>(&Bs[kp][nq]) = t;
        }
    };

    load_tile(0);

    for (int k0 = 0; k0 < K; k0 += BK) {
        commit_tile();
        __syncthreads();

        if (k0 + BK < K) load_tile(k0 + BK);

        #pragma unroll
        for (int ks = 0; ks < KP; ks += 8) {
            uint32_t a[2][4], b[8][2];
            #pragma unroll
            for (int mi = 0; mi < 2; mi++) {
                const int m0 = wm + mi * 16;
                a[mi][0] = As[ks + tg    ][m0 + g    ];
                a[mi][1] = As[ks + tg    ][m0 + g + 8];
                a[mi][2] = As[ks + tg + 4][m0 + g    ];
                a[mi][3] = As[ks + tg + 4][m0 + g + 8];
            }
            #pragma unroll
            for (int ni = 0; ni < 8; ni++) {
                const int n0 = wn + ni * 8;
                b[ni][0] = Bs[ks + tg    ][n0 + g];
                b[ni][1] = Bs[ks + tg + 4][n0 + g];
            }
            #pragma unroll
            for (int mi = 0; mi < 2; mi++)
                #pragma unroll
                for (int ni = 0; ni < 8; ni++) {
                    asm volatile(
                        "mma.sync.aligned.m16n8k16.row.col.f32.f16.f16.f32 "
                        "{%0,%1,%2,%3}, {%4,%5,%6,%7}, {%8,%9}, {%0,%1,%2,%3};"
                        : "+f"(acc[mi][ni][0]), "+f"(acc[mi][ni][1]),
                          "+f"(acc[mi][ni][2]), "+f"(acc[mi][ni][3])
                        : "r"(a[mi][0]), "r"(a[mi][1]), "r"(a[mi][2]), "r"(a[mi][3]),
                          "r"(b[ni][0]), "r"(b[ni][1]));
                }
        }
        __syncthreads();
    }

    #pragma unroll
    for (int mi = 0; mi < 2; mi++) {
        const int row0 = m_base + wm + mi * 16 + g;
        const int row1 = row0 + 8;
        #pragma unroll
        for (int ni = 0; ni < 8; ni++) {
            const int col = n_base + wn + ni * 8 + 2 * tg;
            if (row0 < M) {
                __half2 h = __floats2half2_rn(acc[mi][ni][0], acc[mi][ni][1]);
                *reinterpret_cast<__half2*>(C + (size_t)row0 * N + col) = h;
            }
            if (row1 < M) {
                __half2 h = __floats2half2_rn(acc[mi][ni][2], acc[mi][ni][3]);
                *reinterpret_cast<__half2*>(C + (size_t)row1 * N + col) = h;
            }
        }
    }
}

// ---------------------------------------------------------------------------
// Row-gather (fp16 support): 4 warps per output row.  (R7, proven)
// ---------------------------------------------------------------------------
__global__ __launch_bounds__(256)
void row_gather_kernel(const float* __restrict__ bias,
                       float* __restrict__ out,
                       int n_rows) {
    const int gw   = (blockIdx.x * blockDim.x + threadIdx.x) >> 5;
    const int lane = threadIdx.x & 31;
    const int row  = gw >> 2;
    const int part = gw & 3;
    if (row >= n_rows) return;

    const int s = g_offsets[row];
    const int e = g_offsets[row + 1];
    const int fo = part * 32 + lane;

    float4 acc = make_float4(0.f, 0.f, 0.f, 0.f);

    int i = s;
    for (; i + 3 < e; i += 4) {
        const int2 cv0 = __ldcs(&g_perm[i]);
        const int2 cv1 = __ldcs(&g_perm[i + 1]);
        const int2 cv2 = __ldcs(&g_perm[i + 2]);
        const int2 cv3 = __ldcs(&g_perm[i + 3]);
        const uint2 m0 = __ldg(reinterpret_cast<const uint2*>(
                             g_support + (size_t)cv0.x * D) + fo);
        const uint2 m1 = __ldg(reinterpret_cast<const uint2*>(
                             g_support + (size_t)cv1.x * D) + fo);
        const uint2 m2 = __ldg(reinterpret_cast<const uint2*>(
                             g_support + (size_t)cv2.x * D) + fo);
        const uint2 m3 = __ldg(reinterpret_cast<const uint2*>(
                             g_support + (size_t)cv3.x * D) + fo);
        const float v0 = __int_as_float(cv0.y);
        const float v1 = __int_as_float(cv1.y);
        const float v2 = __int_as_float(cv2.y);
        const float v3 = __int_as_float(cv3.y);

        float2 a0 = __half22float2(*reinterpret_cast<const __half2*>(&m0.x));
        float2 b0 = __half22float2(*reinterpret_cast<const __half2*>(&m0.y));
        float2 a1 = __half22float2(*reinterpret_cast<const __half2*>(&m1.x));
        float2 b1 = __half22float2(*reinterpret_cast<const __half2*>(&m1.y));
        float2 a2 = __half22float2(*reinterpret_cast<const __half2*>(&m2.x));
        float2 b2 = __half22float2(*reinterpret_cast<const __half2*>(&m2.y));
        float2 a3 = __half22float2(*reinterpret_cast<const __half2*>(&m3.x));
        float2 b3 = __half22float2(*reinterpret_cast<const __half2*>(&m3.y));

        acc.x += v0 * a0.x + v1 * a1.x + v2 * a2.x + v3 * a3.x;
        acc.y += v0 * a0.y + v1 * a1.y + v2 * a2.y + v3 * a3.y;
        acc.z += v0 * b0.x + v1 * b1.x + v2 * b2.x + v3 * b3.x;
        acc.w += v0 * b0.y + v1 * b1.y + v2 * b2.y + v3 * b3.y;
    }
    for (; i < e; i++) {
        const int2 cv = __ldcs(&g_perm[i]);
        const float v = __int_as_float(cv.y);
        const uint2 m = __ldg(reinterpret_cast<const uint2*>(
                            g_support + (size_t)cv.x * D) + fo);
        float2 a = __half22float2(*reinterpret_cast<const __half2*>(&m.x));
        float2 b = __half22float2(*reinterpret_cast<const __half2*>(&m.y));
        acc.x += v * a.x;
        acc.y += v * a.y;
        acc.z += v * b.x;
        acc.w += v * b.y;
    }

    const float4 b = __ldg(reinterpret_cast<const float4*>(bias) + fo);
    const float4 r = make_float4(acc.x + b.x, acc.y + b.y,
                                 acc.z + b.z, acc.w + b.w);
    __stcs(reinterpret_cast<float4*>(out + (size_t)row * D) + fo, r);
}

// ========================= Launch ==========================================
extern "C" void kernel_launch(void* const* d_in, const int* in_sizes, int n_in,
                              void* d_out, int out_size) {
    const float* x        = (const float*)d_in[0];
    const int*   adj_rows = (const int*)  d_in[1];
    const int*   adj_cols = (const int*)  d_in[2];
    const float* adj_vals = (const float*)d_in[3];
    const float* weight   = (const float*)d_in[4];
    const float* bias     = (const float*)d_in[5];
    float* out = (float*)d_out;

    const int M = in_sizes[0] / D;   // N_NODES
    const int E = in_sizes[1];       // N_EDGES

    // ---- fork: prep chain on side stream, GEMM on main stream ----
    cudaEventRecord(g_fj.fork_ev, 0);
    cudaStreamWaitEvent(g_fj.side, g_fj.fork_ev, 0);

    zero_counts_kernel<<<(M + 255) / 256, 256, 0, g_fj.side>>>(M);
    hist_kernel<<<(E + 255) / 256, 256, 0, g_fj.side>>>(adj_rows, E);
    const int nb = (M + 511) / 512;
    scan1_kernel<<<nb, 512, 0, g_fj.side>>>(M);
    scan2_kernel<<<1, 128, 0, g_fj.side>>>(nb);
    scan3_kernel<<<nb, 512, 0, g_fj.side>>>(M, E);
    place_kernel<<<(E + 255) / 256, 256, 0, g_fj.side>>>(adj_rows, adj_cols,
                                                         adj_vals, E);
    cudaEventRecord(g_fj.join_ev, g_fj.side);

    // GEMM on the main (capture) stream, concurrent with prep
    {
        __half* support;
        cudaGetSymbolAddress((void**)&support, g_support);
        dim3 grid(D / BN, (M + BM - 1) / BM);
        f16_gemm_kernel<<<grid, 256>>>(x, weight, support, M);
    }

    // ---- join: gather needs both GEMM output and CSR ----
    cudaStreamWaitEvent(0, g_fj.join_ev, 0);
    {
        int total_warps = 4 * M;
        int blocks = (total_warps + 7) / 8;
        row_gather_kernel<<<blocks, 256>>>(bias, out, M);
    }
}